// round 1
// baseline (speedup 1.0000x reference)
#include <cuda_runtime.h>
#include <cstddef>

// Problem shape (fixed by the reference):
//  batch [16,1024,1024] -> M=16384, K=1024
//  W1 [1024,1024], b1[1024]
//  W2 [1024,128],  b2[128]
//  out [16,1024,1024] fp32
#define BM 128
#define BN 128
#define BKK 16
#define TM 8
#define TN 8

static const int M_TOT = 16 * 1024;   // 16384
static const int D_DIM = 1024;
static const int H_DIM = 1024;
static const int R_DIM = 128;
static const int L_DIM = 1024;
static const int B_DIM = 16;

// Scratch in __device__ globals (no runtime allocation allowed).
__device__ float g_h[(size_t)16384 * 1024];   // 64 MiB
__device__ float g_t[(size_t)16384 * 128];    // 8 MiB
__device__ float g_sq[16384];

// ---------------------------------------------------------------------------
// Generic SGEMM: C[M,N] = relu(A[M,K] @ B[K,N] + bias[N])
// A row-major, B row-major. All dims divisible by tile sizes here.
// ---------------------------------------------------------------------------
__global__ __launch_bounds__(256, 2)
void gemm_bias_relu(const float* __restrict__ A, const float* __restrict__ B,
                    const float* __restrict__ bias, float* __restrict__ C,
                    int M, int N, int K) {
    __shared__ float As[BKK][BM + 1];   // transposed tile, +1 pad kills store conflicts
    __shared__ float Bs[BKK][BN];

    const int tid = threadIdx.x;
    const int nBase = blockIdx.x * BN;
    const int mBase = blockIdx.y * BM;
    const int tx = tid % (BN / TN);     // 0..15
    const int ty = tid / (BN / TN);     // 0..15

    float acc[TM][TN];
#pragma unroll
    for (int i = 0; i < TM; i++)
#pragma unroll
        for (int j = 0; j < TN; j++) acc[i][j] = 0.0f;

    // A tile: 128 rows x 16 cols = 512 float4 loads, 2 per thread (transposed scatter)
    const int aRow = tid >> 2;          // 0..63
    const int aCol = (tid & 3) * 4;     // 0,4,8,12
    // B tile: 16 rows x 128 cols = 512 float4 loads, 2 per thread (direct)
    const int bRow = tid >> 5;          // 0..7
    const int bCol = (tid & 31) * 4;    // 0..124

    for (int k0 = 0; k0 < K; k0 += BKK) {
#pragma unroll
        for (int i = 0; i < 2; i++) {
            const int r = aRow + i * 64;
            const float4 v = *reinterpret_cast<const float4*>(
                &A[(size_t)(mBase + r) * K + k0 + aCol]);
            As[aCol + 0][r] = v.x;
            As[aCol + 1][r] = v.y;
            As[aCol + 2][r] = v.z;
            As[aCol + 3][r] = v.w;
        }
#pragma unroll
        for (int i = 0; i < 2; i++) {
            const int r = bRow + i * 8;
            *reinterpret_cast<float4*>(&Bs[r][bCol]) =
                *reinterpret_cast<const float4*>(&B[(size_t)(k0 + r) * N + nBase + bCol]);
        }
        __syncthreads();

#pragma unroll
        for (int k = 0; k < BKK; k++) {
            float rm[TM], rn[TN];
#pragma unroll
            for (int i = 0; i < TM; i++) rm[i] = As[k][ty * TM + i];
#pragma unroll
            for (int j = 0; j < TN; j++) rn[j] = Bs[k][tx * TN + j];
#pragma unroll
            for (int i = 0; i < TM; i++)
#pragma unroll
                for (int j = 0; j < TN; j++)
                    acc[i][j] = fmaf(rm[i], rn[j], acc[i][j]);
        }
        __syncthreads();
    }

#pragma unroll
    for (int i = 0; i < TM; i++) {
        const int row = mBase + ty * TM + i;
#pragma unroll
        for (int j = 0; j < TN; j += 4) {
            const int col = nBase + tx * TN + j;
            float4 v;
            v.x = fmaxf(acc[i][j + 0] + bias[col + 0], 0.0f);
            v.y = fmaxf(acc[i][j + 1] + bias[col + 1], 0.0f);
            v.z = fmaxf(acc[i][j + 2] + bias[col + 2], 0.0f);
            v.w = fmaxf(acc[i][j + 3] + bias[col + 3], 0.0f);
            *reinterpret_cast<float4*>(&C[(size_t)row * N + col]) = v;
        }
    }
}

// ---------------------------------------------------------------------------
// Row squared-norms: sq[m] = sum_r t[m,r]^2   (R = 128)
// One block of 128 threads per row.
// ---------------------------------------------------------------------------
__global__ void sqnorm_kernel(const float* __restrict__ t, float* __restrict__ sq) {
    const int row = blockIdx.x;
    const int lane = threadIdx.x;               // 0..127
    float v = t[(size_t)row * 128 + lane];
    v *= v;
#pragma unroll
    for (int o = 16; o; o >>= 1) v += __shfl_down_sync(0xffffffffu, v, o);
    __shared__ float s[4];
    if ((lane & 31) == 0) s[lane >> 5] = v;
    __syncthreads();
    if (lane == 0) sq[row] = s[0] + s[1] + s[2] + s[3];
}

// ---------------------------------------------------------------------------
// Per-batch pairwise squared distances:
//   out[b,i,j] = max(sq[i] + sq[j] - 2 * dot(t_i, t_j), 0)
// GEMM C = Tb @ Tb^T with K = R = 128. Both tiles loaded transposed-scatter.
// ---------------------------------------------------------------------------
__global__ __launch_bounds__(256, 2)
void pairdist_kernel(const float* __restrict__ t, const float* __restrict__ sq,
                     float* __restrict__ out) {
    const int L = 1024, R = 128;
    const float* Tb  = t  + (size_t)blockIdx.z * L * R;
    const float* sqb = sq + (size_t)blockIdx.z * L;
    float* Ob        = out + (size_t)blockIdx.z * L * L;

    __shared__ float As[BKK][BM + 1];
    __shared__ float Bs[BKK][BN + 1];

    const int tid = threadIdx.x;
    const int jBase = blockIdx.x * BN;
    const int iBase = blockIdx.y * BM;
    const int tx = tid % (BN / TN);
    const int ty = tid / (BN / TN);

    float acc[TM][TN];
#pragma unroll
    for (int i = 0; i < TM; i++)
#pragma unroll
        for (int j = 0; j < TN; j++) acc[i][j] = 0.0f;

    const int aRow = tid >> 2;          // 0..63
    const int aCol = (tid & 3) * 4;     // 0,4,8,12

    for (int k0 = 0; k0 < R; k0 += BKK) {
#pragma unroll
        for (int i = 0; i < 2; i++) {
            const int r = aRow + i * 64;
            {   // rows of Tb for the i-tile (A)
                const float4 v = *reinterpret_cast<const float4*>(
                    &Tb[(size_t)(iBase + r) * R + k0 + aCol]);
                As[aCol + 0][r] = v.x;
                As[aCol + 1][r] = v.y;
                As[aCol + 2][r] = v.z;
                As[aCol + 3][r] = v.w;
            }
            {   // rows of Tb for the j-tile (B = Tb^T)
                const float4 v = *reinterpret_cast<const float4*>(
                    &Tb[(size_t)(jBase + r) * R + k0 + aCol]);
                Bs[aCol + 0][r] = v.x;
                Bs[aCol + 1][r] = v.y;
                Bs[aCol + 2][r] = v.z;
                Bs[aCol + 3][r] = v.w;
            }
        }
        __syncthreads();

#pragma unroll
        for (int k = 0; k < BKK; k++) {
            float rm[TM], rn[TN];
#pragma unroll
            for (int i = 0; i < TM; i++) rm[i] = As[k][ty * TM + i];
#pragma unroll
            for (int j = 0; j < TN; j++) rn[j] = Bs[k][tx * TN + j];
#pragma unroll
            for (int i = 0; i < TM; i++)
#pragma unroll
                for (int j = 0; j < TN; j++)
                    acc[i][j] = fmaf(rm[i], rn[j], acc[i][j]);
        }
        __syncthreads();
    }

#pragma unroll
    for (int i = 0; i < TM; i++) {
        const int row = iBase + ty * TM + i;
        const float si = sqb[row];
#pragma unroll
        for (int j = 0; j < TN; j += 4) {
            const int col = jBase + tx * TN + j;
            float4 v;
            v.x = fmaxf(si + sqb[col + 0] - 2.0f * acc[i][j + 0], 0.0f);
            v.y = fmaxf(si + sqb[col + 1] - 2.0f * acc[i][j + 1], 0.0f);
            v.z = fmaxf(si + sqb[col + 2] - 2.0f * acc[i][j + 2], 0.0f);
            v.w = fmaxf(si + sqb[col + 3] - 2.0f * acc[i][j + 3], 0.0f);
            *reinterpret_cast<float4*>(&Ob[(size_t)row * L + col]) = v;
        }
    }
}

// ---------------------------------------------------------------------------
extern "C" void kernel_launch(void* const* d_in, const int* in_sizes, int n_in,
                              void* d_out, int out_size) {
    const float* batch = (const float*)d_in[0];
    const float* W1    = (const float*)d_in[1];
    const float* b1    = (const float*)d_in[2];
    const float* W2    = (const float*)d_in[3];
    const float* b2    = (const float*)d_in[4];
    float* out = (float*)d_out;

    float *h_ptr, *t_ptr, *sq_ptr;
    cudaGetSymbolAddress((void**)&h_ptr,  g_h);
    cudaGetSymbolAddress((void**)&t_ptr,  g_t);
    cudaGetSymbolAddress((void**)&sq_ptr, g_sq);

    // Stage 1: h = relu(batch @ W1 + b1)   [16384 x 1024] x [1024 x 1024]
    {
        dim3 grid(H_DIM / BN, M_TOT / BM);   // (8, 128)
        gemm_bias_relu<<<grid, 256>>>(batch, W1, b1, h_ptr, M_TOT, H_DIM, D_DIM);
    }
    // Stage 2: t = relu(h @ W2 + b2)       [16384 x 1024] x [1024 x 128]
    {
        dim3 grid(R_DIM / BN, M_TOT / BM);   // (1, 128)
        gemm_bias_relu<<<grid, 256>>>(h_ptr, W2, b2, t_ptr, M_TOT, R_DIM, H_DIM);
    }
    // Stage 3a: row squared norms
    sqnorm_kernel<<<M_TOT, 128>>>(t_ptr, sq_ptr);
    // Stage 3b: per-batch pairwise distances
    {
        dim3 grid(L_DIM / BN, L_DIM / BM, B_DIM);  // (8, 8, 16)
        pairdist_kernel<<<grid, 256>>>(t_ptr, sq_ptr, out);
    }
}

// round 3
// speedup vs baseline: 2.0697x; 2.0697x over previous
#include <cuda_runtime.h>
#include <cuda_bf16.h>
#include <cstdint>
#include <cstddef>

// Shapes: batch[16,1024,1024] -> M=16384,K=1024 ; W1[1024,1024] ; W2[1024,128]
// out[16,1024,1024] fp32.
static const int M_TOT = 16384;
static const int D_DIM = 1024;
static const int H_DIM = 1024;
static const int R_DIM = 128;
static const int L_DIM = 1024;
static const int B_DIM = 16;

// ---- scratch (__device__ globals; no runtime allocation allowed) ----
__device__ __align__(256) __nv_bfloat16 g_a_hi[(size_t)16384 * 1024];
__device__ __align__(256) __nv_bfloat16 g_a_lo[(size_t)16384 * 1024];
__device__ __align__(256) __nv_bfloat16 g_h_hi[(size_t)16384 * 1024];
__device__ __align__(256) __nv_bfloat16 g_h_lo[(size_t)16384 * 1024];
__device__ __align__(256) __nv_bfloat16 g_w1t_hi[(size_t)1024 * 1024];
__device__ __align__(256) __nv_bfloat16 g_w1t_lo[(size_t)1024 * 1024];
__device__ __align__(256) __nv_bfloat16 g_w2t_hi[(size_t)128 * 1024];
__device__ __align__(256) __nv_bfloat16 g_w2t_lo[(size_t)128 * 1024];
__device__ __align__(256) float g_t[(size_t)16384 * 128];
__device__ __align__(256) float g_sq[16384];

// ---------------- PTX helpers (sm_80-era only: ldmatrix / mma.sync / cp.async) ----
__device__ __forceinline__ uint32_t smem_u32(const void* p) {
    uint32_t a;
    asm("{ .reg .u64 t; cvta.to.shared.u64 t, %1; cvt.u32.u64 %0, t; }" : "=r"(a) : "l"(p));
    return a;
}
__device__ __forceinline__ void cp16(uint32_t saddr, const void* g) {
    asm volatile("cp.async.cg.shared.global [%0], [%1], 16;" :: "r"(saddr), "l"(g));
}
__device__ __forceinline__ void cp_commit() {
    asm volatile("cp.async.commit_group;" ::: "memory");
}
__device__ __forceinline__ void cp_wait1() {
    asm volatile("cp.async.wait_group 1;" ::: "memory");
}
__device__ __forceinline__ void ldsm4(uint32_t* r, uint32_t addr) {
    asm volatile("ldmatrix.sync.aligned.m8n8.x4.shared.b16 {%0,%1,%2,%3}, [%4];"
                 : "=r"(r[0]), "=r"(r[1]), "=r"(r[2]), "=r"(r[3]) : "r"(addr));
}
__device__ __forceinline__ void mma_bf16(float* c, const uint32_t* a, const uint32_t* b) {
    asm volatile(
        "mma.sync.aligned.m16n8k16.row.col.f32.bf16.bf16.f32 "
        "{%0,%1,%2,%3}, {%4,%5,%6,%7}, {%8,%9}, {%0,%1,%2,%3};"
        : "+f"(c[0]), "+f"(c[1]), "+f"(c[2]), "+f"(c[3])
        : "r"(a[0]), "r"(a[1]), "r"(a[2]), "r"(a[3]), "r"(b[0]), "r"(b[1]));
}

// ---------------- tensor-core GEMM via mma.sync -------------------------------
// C[M,N] = relu(A @ Wt^T + bias); A split bf16 [M,K] (hi/lo), Wt split bf16 [N,K].
// OUT_SPLIT: emit C as bf16 hi/lo pair; else fp32.
// Tiles: BM=128, BN=128, BK=32. 8 warps: warp_m=wid&3 (32 rows), warp_n=wid>>2 (64 cols).
// smem per stage: A_hi, A_lo, B_hi, B_lo each 128 rows x 80B (64B data + 16B pad).
static const int ROWB = 80;            // padded row stride in bytes
static const int OFF_ALO = 10240;
static const int OFF_BHI = 20480;
static const int OFF_BLO = 30720;
static const int STAGE = 40960;
static const int MMA_SMEM = 2 * STAGE; // 81920

template <bool OUT_SPLIT>
__global__ __launch_bounds__(256)
void mma_gemm(const __nv_bfloat16* __restrict__ Ahi, const __nv_bfloat16* __restrict__ Alo,
              const __nv_bfloat16* __restrict__ Bhi, const __nv_bfloat16* __restrict__ Blo,
              const float* __restrict__ bias,
              float* __restrict__ Cf,
              __nv_bfloat16* __restrict__ Chi, __nv_bfloat16* __restrict__ Clo,
              int K, int Ncols) {
    extern __shared__ char smem[];
    const uint32_t sbase = smem_u32(smem);
    const int tid = threadIdx.x;
    const int lane = tid & 31;
    const int wid = tid >> 5;
    const int warp_m = wid & 3;
    const int warp_n = wid >> 2;

    const int mBase = blockIdx.y * 128;
    const int nBase = blockIdx.x * 128;
    const int NC = K >> 5;   // chunks of 32

    float acc[2][8][4];
#pragma unroll
    for (int i = 0; i < 2; i++)
#pragma unroll
        for (int j = 0; j < 8; j++)
#pragma unroll
            for (int q = 0; q < 4; q++) acc[i][j][q] = 0.0f;

    // per-thread load coords (2 iters of 256 threads cover 128 rows x 4 segs)
    const int lrow0 = tid >> 2;
    const int lseg = tid & 3;

    auto load_chunk = [&](int k0, int soff) {
#pragma unroll
        for (int i = 0; i < 2; ++i) {
            const int row = lrow0 + i * 64;
            const size_t aoff = (size_t)(mBase + row) * K + k0 + lseg * 8;
            const size_t boff = (size_t)(nBase + row) * K + k0 + lseg * 8;
            const uint32_t s = sbase + soff + row * ROWB + lseg * 16;
            cp16(s,           Ahi + aoff);
            cp16(s + OFF_ALO, Alo + aoff);
            cp16(s + OFF_BHI, Bhi + boff);
            cp16(s + OFF_BLO, Blo + boff);
        }
    };

    load_chunk(0, 0);  cp_commit();
    if (NC > 1) load_chunk(32, STAGE);
    cp_commit();

    // ldmatrix lane-address components
    const int a_row_off = lane & 15;            // row within 16
    const int a_k_off = (lane >> 4) << 3;       // 0 or 8
    const int b_n_off = (lane & 7) + ((lane >> 4) << 3);
    const int b_k_off = ((lane >> 3) & 1) << 3;

    for (int c = 0; c < NC; ++c) {
        cp_wait1();
        __syncthreads();
        const uint32_t base = sbase + (c & 1) * STAGE;
#pragma unroll
        for (int ks = 0; ks < 2; ++ks) {
            uint32_t Ah[2][4], Al[2][4];
#pragma unroll
            for (int mi = 0; mi < 2; ++mi) {
                const int row = warp_m * 32 + mi * 16 + a_row_off;
                const uint32_t addr = base + row * ROWB + ((ks * 16 + a_k_off) << 1);
                ldsm4(Ah[mi], addr);
                ldsm4(Al[mi], addr + OFF_ALO);
            }
#pragma unroll
            for (int np = 0; np < 4; ++np) {
                uint32_t Bh[4], Bl[4];
                const int n = warp_n * 64 + np * 16 + b_n_off;
                const uint32_t addr = base + OFF_BHI + n * ROWB + ((ks * 16 + b_k_off) << 1);
                ldsm4(Bh, addr);
                ldsm4(Bl, addr + 10240);   // B_lo sits 10240 past B_hi
#pragma unroll
                for (int half = 0; half < 2; ++half) {
                    const uint32_t bh[2] = {Bh[half * 2], Bh[half * 2 + 1]};
                    const uint32_t bl[2] = {Bl[half * 2], Bl[half * 2 + 1]};
#pragma unroll
                    for (int mi = 0; mi < 2; ++mi) {
                        float* cc = acc[mi][np * 2 + half];
                        mma_bf16(cc, Ah[mi], bh);
                        mma_bf16(cc, Ah[mi], bl);
                        mma_bf16(cc, Al[mi], bh);
                    }
                }
            }
        }
        __syncthreads();
        if (c + 2 < NC) load_chunk((c + 2) << 5, (c & 1) * STAGE);
        cp_commit();
    }

    // ---------------- epilogue ----------------
#pragma unroll
    for (int mi = 0; mi < 2; ++mi) {
        const int r0 = mBase + warp_m * 32 + mi * 16 + (lane >> 2);
#pragma unroll
        for (int ni = 0; ni < 8; ++ni) {
            const int col = nBase + warp_n * 64 + ni * 8 + 2 * (lane & 3);
            const float bz0 = bias[col], bz1 = bias[col + 1];
            const float* cc = acc[mi][ni];
            const float v00 = fmaxf(cc[0] + bz0, 0.f), v01 = fmaxf(cc[1] + bz1, 0.f);
            const float v10 = fmaxf(cc[2] + bz0, 0.f), v11 = fmaxf(cc[3] + bz1, 0.f);
            if (OUT_SPLIT) {
                __nv_bfloat16 h00 = __float2bfloat16(v00), h01 = __float2bfloat16(v01);
                __nv_bfloat16 h10 = __float2bfloat16(v10), h11 = __float2bfloat16(v11);
                __nv_bfloat16 l00 = __float2bfloat16(v00 - __bfloat162float(h00));
                __nv_bfloat16 l01 = __float2bfloat16(v01 - __bfloat162float(h01));
                __nv_bfloat16 l10 = __float2bfloat16(v10 - __bfloat162float(h10));
                __nv_bfloat16 l11 = __float2bfloat16(v11 - __bfloat162float(h11));
                __nv_bfloat162 hp0 = __halves2bfloat162(h00, h01);
                __nv_bfloat162 hp1 = __halves2bfloat162(h10, h11);
                __nv_bfloat162 lp0 = __halves2bfloat162(l00, l01);
                __nv_bfloat162 lp1 = __halves2bfloat162(l10, l11);
                *reinterpret_cast<uint32_t*>(Chi + (size_t)r0 * Ncols + col) =
                    *reinterpret_cast<uint32_t*>(&hp0);
                *reinterpret_cast<uint32_t*>(Chi + (size_t)(r0 + 8) * Ncols + col) =
                    *reinterpret_cast<uint32_t*>(&hp1);
                *reinterpret_cast<uint32_t*>(Clo + (size_t)r0 * Ncols + col) =
                    *reinterpret_cast<uint32_t*>(&lp0);
                *reinterpret_cast<uint32_t*>(Clo + (size_t)(r0 + 8) * Ncols + col) =
                    *reinterpret_cast<uint32_t*>(&lp1);
            } else {
                *reinterpret_cast<float2*>(Cf + (size_t)r0 * Ncols + col) =
                    make_float2(v00, v01);
                *reinterpret_cast<float2*>(Cf + (size_t)(r0 + 8) * Ncols + col) =
                    make_float2(v10, v11);
            }
        }
    }
}

// ---------------- conversion kernels ----------------
__global__ void split_kernel(const float* __restrict__ x,
                             __nv_bfloat16* __restrict__ hi,
                             __nv_bfloat16* __restrict__ lo, int n4) {
    int i = blockIdx.x * 256 + threadIdx.x;
    if (i >= n4) return;
    float4 v = reinterpret_cast<const float4*>(x)[i];
    __nv_bfloat16 h0 = __float2bfloat16(v.x), h1 = __float2bfloat16(v.y);
    __nv_bfloat16 h2 = __float2bfloat16(v.z), h3 = __float2bfloat16(v.w);
    __nv_bfloat16 l0 = __float2bfloat16(v.x - __bfloat162float(h0));
    __nv_bfloat16 l1 = __float2bfloat16(v.y - __bfloat162float(h1));
    __nv_bfloat16 l2 = __float2bfloat16(v.z - __bfloat162float(h2));
    __nv_bfloat16 l3 = __float2bfloat16(v.w - __bfloat162float(h3));
    __nv_bfloat162 hp0 = __halves2bfloat162(h0, h1), hp1 = __halves2bfloat162(h2, h3);
    __nv_bfloat162 lp0 = __halves2bfloat162(l0, l1), lp1 = __halves2bfloat162(l2, l3);
    reinterpret_cast<uint2*>(hi)[i] =
        make_uint2(*reinterpret_cast<uint32_t*>(&hp0), *reinterpret_cast<uint32_t*>(&hp1));
    reinterpret_cast<uint2*>(lo)[i] =
        make_uint2(*reinterpret_cast<uint32_t*>(&lp0), *reinterpret_cast<uint32_t*>(&lp1));
}

// W[K,N] fp32 -> Wt_hi/lo[N,K] bf16 (transposed split)
__global__ void transpose_split_kernel(const float* __restrict__ W,
                                       __nv_bfloat16* __restrict__ th,
                                       __nv_bfloat16* __restrict__ tl, int K, int N) {
    int idx = blockIdx.x * 256 + threadIdx.x;
    if (idx >= K * N) return;
    int k = idx / N, n = idx - k * N;
    float v = W[idx];
    __nv_bfloat16 h = __float2bfloat16(v);
    th[(size_t)n * K + k] = h;
    tl[(size_t)n * K + k] = __float2bfloat16(v - __bfloat162float(h));
}

// ---------------- stage 3 (SIMT, unchanged) ----------------
__global__ void sqnorm_kernel(const float* __restrict__ t, float* __restrict__ sq) {
    const int row = blockIdx.x;
    const int lane = threadIdx.x;
    float v = t[(size_t)row * 128 + lane];
    v *= v;
#pragma unroll
    for (int o = 16; o; o >>= 1) v += __shfl_down_sync(0xffffffffu, v, o);
    __shared__ float s[4];
    if ((lane & 31) == 0) s[lane >> 5] = v;
    __syncthreads();
    if (lane == 0) sq[row] = s[0] + s[1] + s[2] + s[3];
}

#define BM 128
#define BN 128
#define BKK 16
#define TM 8
#define TN 8
__global__ __launch_bounds__(256, 2)
void pairdist_kernel(const float* __restrict__ t, const float* __restrict__ sq,
                     float* __restrict__ out) {
    const int L = 1024, R = 128;
    const float* Tb  = t  + (size_t)blockIdx.z * L * R;
    const float* sqb = sq + (size_t)blockIdx.z * L;
    float* Ob        = out + (size_t)blockIdx.z * L * L;

    __shared__ float As[BKK][BM + 1];
    __shared__ float Bs[BKK][BN + 1];

    const int tid = threadIdx.x;
    const int jBase = blockIdx.x * BN;
    const int iBase = blockIdx.y * BM;
    const int tx = tid % (BN / TN);
    const int ty = tid / (BN / TN);

    float acc[TM][TN];
#pragma unroll
    for (int i = 0; i < TM; i++)
#pragma unroll
        for (int j = 0; j < TN; j++) acc[i][j] = 0.0f;

    const int aRow = tid >> 2;
    const int aCol = (tid & 3) * 4;

    for (int k0 = 0; k0 < R; k0 += BKK) {
#pragma unroll
        for (int i = 0; i < 2; i++) {
            const int r = aRow + i * 64;
            {
                const float4 v = *reinterpret_cast<const float4*>(
                    &Tb[(size_t)(iBase + r) * R + k0 + aCol]);
                As[aCol + 0][r] = v.x; As[aCol + 1][r] = v.y;
                As[aCol + 2][r] = v.z; As[aCol + 3][r] = v.w;
            }
            {
                const float4 v = *reinterpret_cast<const float4*>(
                    &Tb[(size_t)(jBase + r) * R + k0 + aCol]);
                Bs[aCol + 0][r] = v.x; Bs[aCol + 1][r] = v.y;
                Bs[aCol + 2][r] = v.z; Bs[aCol + 3][r] = v.w;
            }
        }
        __syncthreads();

#pragma unroll
        for (int k = 0; k < BKK; k++) {
            float rm[TM], rn[TN];
#pragma unroll
            for (int i = 0; i < TM; i++) rm[i] = As[k][ty * TM + i];
#pragma unroll
            for (int j = 0; j < TN; j++) rn[j] = Bs[k][tx * TN + j];
#pragma unroll
            for (int i = 0; i < TM; i++)
#pragma unroll
                for (int j = 0; j < TN; j++)
                    acc[i][j] = fmaf(rm[i], rn[j], acc[i][j]);
        }
        __syncthreads();
    }

#pragma unroll
    for (int i = 0; i < TM; i++) {
        const int row = iBase + ty * TM + i;
        const float si = sqb[row];
#pragma unroll
        for (int j = 0; j < TN; j += 4) {
            const int col = jBase + tx * TN + j;
            float4 v;
            v.x = fmaxf(si + sqb[col + 0] - 2.0f * acc[i][j + 0], 0.0f);
            v.y = fmaxf(si + sqb[col + 1] - 2.0f * acc[i][j + 1], 0.0f);
            v.z = fmaxf(si + sqb[col + 2] - 2.0f * acc[i][j + 2], 0.0f);
            v.w = fmaxf(si + sqb[col + 3] - 2.0f * acc[i][j + 3], 0.0f);
            *reinterpret_cast<float4*>(&Ob[(size_t)row * L + col]) = v;
        }
    }
}

// ---------------------------------------------------------------------------
extern "C" void kernel_launch(void* const* d_in, const int* in_sizes, int n_in,
                              void* d_out, int out_size) {
    const float* batch = (const float*)d_in[0];
    const float* W1    = (const float*)d_in[1];
    const float* b1    = (const float*)d_in[2];
    const float* W2    = (const float*)d_in[3];
    const float* b2    = (const float*)d_in[4];
    float* out = (float*)d_out;

    __nv_bfloat16 *a_hi, *a_lo, *h_hi, *h_lo, *w1t_hi, *w1t_lo, *w2t_hi, *w2t_lo;
    float *t_ptr, *sq_ptr;
    cudaGetSymbolAddress((void**)&a_hi,   g_a_hi);
    cudaGetSymbolAddress((void**)&a_lo,   g_a_lo);
    cudaGetSymbolAddress((void**)&h_hi,   g_h_hi);
    cudaGetSymbolAddress((void**)&h_lo,   g_h_lo);
    cudaGetSymbolAddress((void**)&w1t_hi, g_w1t_hi);
    cudaGetSymbolAddress((void**)&w1t_lo, g_w1t_lo);
    cudaGetSymbolAddress((void**)&w2t_hi, g_w2t_hi);
    cudaGetSymbolAddress((void**)&w2t_lo, g_w2t_lo);
    cudaGetSymbolAddress((void**)&t_ptr,  g_t);
    cudaGetSymbolAddress((void**)&sq_ptr, g_sq);

    cudaFuncSetAttribute(mma_gemm<true>,  cudaFuncAttributeMaxDynamicSharedMemorySize, MMA_SMEM);
    cudaFuncSetAttribute(mma_gemm<false>, cudaFuncAttributeMaxDynamicSharedMemorySize, MMA_SMEM);

    // 0) precision splits
    {
        int n4 = M_TOT * D_DIM / 4;
        split_kernel<<<(n4 + 255) / 256, 256>>>(batch, a_hi, a_lo, n4);
        transpose_split_kernel<<<(D_DIM * H_DIM + 255) / 256, 256>>>(W1, w1t_hi, w1t_lo, D_DIM, H_DIM);
        transpose_split_kernel<<<(H_DIM * R_DIM + 255) / 256, 256>>>(W2, w2t_hi, w2t_lo, H_DIM, R_DIM);
    }
    // 1) h = relu(batch @ W1 + b1) -> bf16 hi/lo
    {
        dim3 grid(H_DIM / 128, M_TOT / 128);   // (8, 128)
        mma_gemm<true><<<grid, 256, MMA_SMEM>>>(
            a_hi, a_lo, w1t_hi, w1t_lo, b1, nullptr, h_hi, h_lo, D_DIM, H_DIM);
    }
    // 2) t = relu(h @ W2 + b2) -> fp32
    {
        dim3 grid(R_DIM / 128, M_TOT / 128);   // (1, 128)
        mma_gemm<false><<<grid, 256, MMA_SMEM>>>(
            h_hi, h_lo, w2t_hi, w2t_lo, b2, t_ptr, nullptr, nullptr, H_DIM, R_DIM);
    }
    // 3) pairwise distances
    sqnorm_kernel<<<M_TOT, 128>>>(t_ptr, sq_ptr);
    {
        dim3 grid(L_DIM / BN, L_DIM / BM, B_DIM);
        pairdist_kernel<<<grid, 256>>>(t_ptr, sq_ptr, out);
    }
}

// round 4
// speedup vs baseline: 2.5509x; 1.2325x over previous
#include <cuda_runtime.h>
#include <cuda_bf16.h>
#include <cstdint>
#include <cstddef>

// Shapes: batch[16,1024,1024] -> M=16384,K=1024 ; W1[1024,1024] ; W2[1024,128]
// out[16,1024,1024] fp32.
static const int M_TOT = 16384;
static const int D_DIM = 1024;
static const int H_DIM = 1024;
static const int R_DIM = 128;
static const int L_DIM = 1024;
static const int B_DIM = 16;

// ---- scratch (__device__ globals; no runtime allocation allowed) ----
__device__ __align__(256) __nv_bfloat16 g_a_hi[(size_t)16384 * 1024];
__device__ __align__(256) __nv_bfloat16 g_a_lo[(size_t)16384 * 1024];
__device__ __align__(256) __nv_bfloat16 g_h_hi[(size_t)16384 * 1024];
__device__ __align__(256) __nv_bfloat16 g_h_lo[(size_t)16384 * 1024];
__device__ __align__(256) __nv_bfloat16 g_w1t_hi[(size_t)1024 * 1024];
__device__ __align__(256) __nv_bfloat16 g_w1t_lo[(size_t)1024 * 1024];
__device__ __align__(256) __nv_bfloat16 g_w2t_hi[(size_t)128 * 1024];
__device__ __align__(256) __nv_bfloat16 g_w2t_lo[(size_t)128 * 1024];
__device__ __align__(256) __nv_bfloat16 g_t_hi[(size_t)16384 * 128];
__device__ __align__(256) __nv_bfloat16 g_t_lo[(size_t)16384 * 128];
__device__ __align__(256) float g_sq[16384];

// ---------------- PTX helpers (sm_80-era only: ldmatrix / mma.sync / cp.async) ----
__device__ __forceinline__ uint32_t smem_u32(const void* p) {
    uint32_t a;
    asm("{ .reg .u64 t; cvta.to.shared.u64 t, %1; cvt.u32.u64 %0, t; }" : "=r"(a) : "l"(p));
    return a;
}
__device__ __forceinline__ void cp16(uint32_t saddr, const void* g) {
    asm volatile("cp.async.cg.shared.global [%0], [%1], 16;" :: "r"(saddr), "l"(g));
}
__device__ __forceinline__ void cp_commit() {
    asm volatile("cp.async.commit_group;" ::: "memory");
}
__device__ __forceinline__ void cp_wait1() {
    asm volatile("cp.async.wait_group 1;" ::: "memory");
}
__device__ __forceinline__ void ldsm4(uint32_t* r, uint32_t addr) {
    asm volatile("ldmatrix.sync.aligned.m8n8.x4.shared.b16 {%0,%1,%2,%3}, [%4];"
                 : "=r"(r[0]), "=r"(r[1]), "=r"(r[2]), "=r"(r[3]) : "r"(addr));
}
__device__ __forceinline__ void mma_bf16(float* c, const uint32_t* a, const uint32_t* b) {
    asm volatile(
        "mma.sync.aligned.m16n8k16.row.col.f32.bf16.bf16.f32 "
        "{%0,%1,%2,%3}, {%4,%5,%6,%7}, {%8,%9}, {%0,%1,%2,%3};"
        : "+f"(c[0]), "+f"(c[1]), "+f"(c[2]), "+f"(c[3])
        : "r"(a[0]), "r"(a[1]), "r"(a[2]), "r"(a[3]), "r"(b[0]), "r"(b[1]));
}

// ---------------- unified tensor-core GEMM via mma.sync ------------------------
// acc = A @ B^T with split bf16 operands (hi/lo, 3 products, fp32 accumulate).
// MODE 0 (GEMM1): C = relu(acc + bias) -> bf16 hi/lo pair (Chi/Clo)
// MODE 1 (GEMM2): C = relu(acc + bias) -> bf16 hi/lo pair + per-row sumsq -> Cf(=g_sq)
// MODE 2 (DIST):  per-batch z: out = max(sq[i] + sq[j] - 2*acc, 0) -> Cf; bias = sq
// Tiles: BM=128, BN=128, BK=32. 8 warps: warp_m=wid&3 (32 rows), warp_n=wid>>2 (64 cols).
static const int ROWB = 80;            // padded smem row stride in bytes
static const int OFF_ALO = 10240;
static const int OFF_BHI = 20480;
static const int OFF_BLO = 30720;
static const int STAGE = 40960;
static const int MMA_SMEM = 2 * STAGE + 512;   // + per-row sq scratch (MODE 1)

template <int MODE>
__global__ __launch_bounds__(256, 2)
void mma_gemm(const __nv_bfloat16* __restrict__ Ahi, const __nv_bfloat16* __restrict__ Alo,
              const __nv_bfloat16* __restrict__ Bhi, const __nv_bfloat16* __restrict__ Blo,
              const float* __restrict__ bias,
              float* __restrict__ Cf,
              __nv_bfloat16* __restrict__ Chi, __nv_bfloat16* __restrict__ Clo,
              int K, int Ncols) {
    extern __shared__ char smem[];
    const uint32_t sbase = smem_u32(smem);
    float* sq_s = reinterpret_cast<float*>(smem + 2 * STAGE);
    const int tid = threadIdx.x;
    const int lane = tid & 31;
    const int wid = tid >> 5;
    const int warp_m = wid & 3;
    const int warp_n = wid >> 2;

    const int mBase = blockIdx.y * 128;
    const int nBase = blockIdx.x * 128;
    const int zb = (MODE == 2) ? blockIdx.z : 0;
    const size_t zrow = (size_t)zb * 1024;     // row offset into A/B for batched dist
    const int NC = K >> 5;                     // chunks of 32

    if (MODE == 1 && tid < 128) sq_s[tid] = 0.0f;

    float acc[2][8][4];
#pragma unroll
    for (int i = 0; i < 2; i++)
#pragma unroll
        for (int j = 0; j < 8; j++)
#pragma unroll
            for (int q = 0; q < 4; q++) acc[i][j][q] = 0.0f;

    const int lrow0 = tid >> 2;
    const int lseg = tid & 3;

    auto load_chunk = [&](int k0, int soff) {
#pragma unroll
        for (int i = 0; i < 2; ++i) {
            const int row = lrow0 + i * 64;
            const size_t aoff = (zrow + mBase + row) * K + k0 + lseg * 8;
            const size_t boff = (zrow + nBase + row) * K + k0 + lseg * 8;
            const uint32_t s = sbase + soff + row * ROWB + lseg * 16;
            cp16(s,           Ahi + aoff);
            cp16(s + OFF_ALO, Alo + aoff);
            cp16(s + OFF_BHI, Bhi + boff);
            cp16(s + OFF_BLO, Blo + boff);
        }
    };

    load_chunk(0, 0);  cp_commit();
    if (NC > 1) load_chunk(32, STAGE);
    cp_commit();

    const int a_row_off = lane & 15;
    const int a_k_off = (lane >> 4) << 3;
    const int b_n_off = (lane & 7) + ((lane >> 4) << 3);
    const int b_k_off = ((lane >> 3) & 1) << 3;

    for (int c = 0; c < NC; ++c) {
        cp_wait1();
        __syncthreads();
        const uint32_t base = sbase + (c & 1) * STAGE;
#pragma unroll
        for (int ks = 0; ks < 2; ++ks) {
            uint32_t Ah[2][4], Al[2][4];
#pragma unroll
            for (int mi = 0; mi < 2; ++mi) {
                const int row = warp_m * 32 + mi * 16 + a_row_off;
                const uint32_t addr = base + row * ROWB + ((ks * 16 + a_k_off) << 1);
                ldsm4(Ah[mi], addr);
                ldsm4(Al[mi], addr + OFF_ALO);
            }
#pragma unroll
            for (int np = 0; np < 4; ++np) {
                uint32_t Bh[4], Bl[4];
                const int n = warp_n * 64 + np * 16 + b_n_off;
                const uint32_t addr = base + OFF_BHI + n * ROWB + ((ks * 16 + b_k_off) << 1);
                ldsm4(Bh, addr);
                ldsm4(Bl, addr + 10240);
#pragma unroll
                for (int half = 0; half < 2; ++half) {
                    const uint32_t bh[2] = {Bh[half * 2], Bh[half * 2 + 1]};
                    const uint32_t bl[2] = {Bl[half * 2], Bl[half * 2 + 1]};
#pragma unroll
                    for (int mi = 0; mi < 2; ++mi) {
                        float* cc = acc[mi][np * 2 + half];
                        mma_bf16(cc, Ah[mi], bh);
                        mma_bf16(cc, Ah[mi], bl);
                        mma_bf16(cc, Al[mi], bh);
                    }
                }
            }
        }
        __syncthreads();
        if (c + 2 < NC) load_chunk((c + 2) << 5, (c & 1) * STAGE);
        cp_commit();
    }

    // ---------------- epilogue ----------------
    if (MODE == 2) {
        const float* sqg = bias + zb * 1024;
        float* Ob = Cf + (size_t)zb * 1024 * 1024;
#pragma unroll
        for (int mi = 0; mi < 2; ++mi) {
            const int r0 = mBase + warp_m * 32 + mi * 16 + (lane >> 2);
            const float sr0 = sqg[r0], sr1 = sqg[r0 + 8];
#pragma unroll
            for (int ni = 0; ni < 8; ++ni) {
                const int col = nBase + warp_n * 64 + ni * 8 + 2 * (lane & 3);
                const float sc0 = sqg[col], sc1 = sqg[col + 1];
                const float* cc = acc[mi][ni];
                *reinterpret_cast<float2*>(Ob + (size_t)r0 * Ncols + col) =
                    make_float2(fmaxf(sr0 + sc0 - 2.0f * cc[0], 0.f),
                                fmaxf(sr0 + sc1 - 2.0f * cc[1], 0.f));
                *reinterpret_cast<float2*>(Ob + (size_t)(r0 + 8) * Ncols + col) =
                    make_float2(fmaxf(sr1 + sc0 - 2.0f * cc[2], 0.f),
                                fmaxf(sr1 + sc1 - 2.0f * cc[3], 0.f));
            }
        }
    } else {
#pragma unroll
        for (int mi = 0; mi < 2; ++mi) {
            const int r0 = mBase + warp_m * 32 + mi * 16 + (lane >> 2);
            float ss0 = 0.0f, ss1 = 0.0f;
#pragma unroll
            for (int ni = 0; ni < 8; ++ni) {
                const int col = nBase + warp_n * 64 + ni * 8 + 2 * (lane & 3);
                const float bz0 = bias[col], bz1 = bias[col + 1];
                const float* cc = acc[mi][ni];
                const float v00 = fmaxf(cc[0] + bz0, 0.f), v01 = fmaxf(cc[1] + bz1, 0.f);
                const float v10 = fmaxf(cc[2] + bz0, 0.f), v11 = fmaxf(cc[3] + bz1, 0.f);
                if (MODE == 1) { ss0 += v00 * v00 + v01 * v01; ss1 += v10 * v10 + v11 * v11; }
                __nv_bfloat16 h00 = __float2bfloat16(v00), h01 = __float2bfloat16(v01);
                __nv_bfloat16 h10 = __float2bfloat16(v10), h11 = __float2bfloat16(v11);
                __nv_bfloat16 l00 = __float2bfloat16(v00 - __bfloat162float(h00));
                __nv_bfloat16 l01 = __float2bfloat16(v01 - __bfloat162float(h01));
                __nv_bfloat16 l10 = __float2bfloat16(v10 - __bfloat162float(h10));
                __nv_bfloat16 l11 = __float2bfloat16(v11 - __bfloat162float(h11));
                __nv_bfloat162 hp0 = __halves2bfloat162(h00, h01);
                __nv_bfloat162 hp1 = __halves2bfloat162(h10, h11);
                __nv_bfloat162 lp0 = __halves2bfloat162(l00, l01);
                __nv_bfloat162 lp1 = __halves2bfloat162(l10, l11);
                *reinterpret_cast<uint32_t*>(Chi + (size_t)r0 * Ncols + col) =
                    *reinterpret_cast<uint32_t*>(&hp0);
                *reinterpret_cast<uint32_t*>(Chi + (size_t)(r0 + 8) * Ncols + col) =
                    *reinterpret_cast<uint32_t*>(&hp1);
                *reinterpret_cast<uint32_t*>(Clo + (size_t)r0 * Ncols + col) =
                    *reinterpret_cast<uint32_t*>(&lp0);
                *reinterpret_cast<uint32_t*>(Clo + (size_t)(r0 + 8) * Ncols + col) =
                    *reinterpret_cast<uint32_t*>(&lp1);
            }
            if (MODE == 1) {
                atomicAdd(&sq_s[r0 - mBase], ss0);
                atomicAdd(&sq_s[r0 + 8 - mBase], ss1);
            }
        }
        if (MODE == 1) {
            __syncthreads();
            if (tid < 128) Cf[mBase + tid] = sq_s[tid];
        }
    }
}

// ---------------- conversion kernels ----------------
__global__ void split_kernel(const float* __restrict__ x,
                             __nv_bfloat16* __restrict__ hi,
                             __nv_bfloat16* __restrict__ lo, int n4) {
    int i = blockIdx.x * 256 + threadIdx.x;
    if (i >= n4) return;
    float4 v = reinterpret_cast<const float4*>(x)[i];
    __nv_bfloat16 h0 = __float2bfloat16(v.x), h1 = __float2bfloat16(v.y);
    __nv_bfloat16 h2 = __float2bfloat16(v.z), h3 = __float2bfloat16(v.w);
    __nv_bfloat16 l0 = __float2bfloat16(v.x - __bfloat162float(h0));
    __nv_bfloat16 l1 = __float2bfloat16(v.y - __bfloat162float(h1));
    __nv_bfloat16 l2 = __float2bfloat16(v.z - __bfloat162float(h2));
    __nv_bfloat16 l3 = __float2bfloat16(v.w - __bfloat162float(h3));
    __nv_bfloat162 hp0 = __halves2bfloat162(h0, h1), hp1 = __halves2bfloat162(h2, h3);
    __nv_bfloat162 lp0 = __halves2bfloat162(l0, l1), lp1 = __halves2bfloat162(l2, l3);
    reinterpret_cast<uint2*>(hi)[i] =
        make_uint2(*reinterpret_cast<uint32_t*>(&hp0), *reinterpret_cast<uint32_t*>(&hp1));
    reinterpret_cast<uint2*>(lo)[i] =
        make_uint2(*reinterpret_cast<uint32_t*>(&lp0), *reinterpret_cast<uint32_t*>(&lp1));
}

// W[K,N] fp32 -> Wt_hi/lo[N,K] bf16 (transposed split), 32x32 smem tiles.
__global__ void transpose_split_kernel(const float* __restrict__ W,
                                       __nv_bfloat16* __restrict__ th,
                                       __nv_bfloat16* __restrict__ tl, int K, int N) {
    __shared__ float tile[32][33];
    const int kb = blockIdx.y * 32;
    const int nb = blockIdx.x * 32;
    const int tx = threadIdx.x, ty = threadIdx.y;   // block (32, 8)
#pragma unroll
    for (int i = 0; i < 4; ++i)
        tile[ty + i * 8][tx] = W[(size_t)(kb + ty + i * 8) * N + nb + tx];
    __syncthreads();
#pragma unroll
    for (int i = 0; i < 4; ++i) {
        const int n = nb + ty + i * 8;
        const int k = kb + tx;
        const float v = tile[tx][ty + i * 8];
        __nv_bfloat16 h = __float2bfloat16(v);
        th[(size_t)n * K + k] = h;
        tl[(size_t)n * K + k] = __float2bfloat16(v - __bfloat162float(h));
    }
}

// ---------------------------------------------------------------------------
extern "C" void kernel_launch(void* const* d_in, const int* in_sizes, int n_in,
                              void* d_out, int out_size) {
    const float* batch = (const float*)d_in[0];
    const float* W1    = (const float*)d_in[1];
    const float* b1    = (const float*)d_in[2];
    const float* W2    = (const float*)d_in[3];
    const float* b2    = (const float*)d_in[4];
    float* out = (float*)d_out;

    __nv_bfloat16 *a_hi, *a_lo, *h_hi, *h_lo, *w1t_hi, *w1t_lo, *w2t_hi, *w2t_lo, *t_hi, *t_lo;
    float *sq_ptr;
    cudaGetSymbolAddress((void**)&a_hi,   g_a_hi);
    cudaGetSymbolAddress((void**)&a_lo,   g_a_lo);
    cudaGetSymbolAddress((void**)&h_hi,   g_h_hi);
    cudaGetSymbolAddress((void**)&h_lo,   g_h_lo);
    cudaGetSymbolAddress((void**)&w1t_hi, g_w1t_hi);
    cudaGetSymbolAddress((void**)&w1t_lo, g_w1t_lo);
    cudaGetSymbolAddress((void**)&w2t_hi, g_w2t_hi);
    cudaGetSymbolAddress((void**)&w2t_lo, g_w2t_lo);
    cudaGetSymbolAddress((void**)&t_hi,   g_t_hi);
    cudaGetSymbolAddress((void**)&t_lo,   g_t_lo);
    cudaGetSymbolAddress((void**)&sq_ptr, g_sq);

    cudaFuncSetAttribute(mma_gemm<0>, cudaFuncAttributeMaxDynamicSharedMemorySize, MMA_SMEM);
    cudaFuncSetAttribute(mma_gemm<1>, cudaFuncAttributeMaxDynamicSharedMemorySize, MMA_SMEM);
    cudaFuncSetAttribute(mma_gemm<2>, cudaFuncAttributeMaxDynamicSharedMemorySize, MMA_SMEM);

    // 0) precision splits
    {
        int n4 = M_TOT * D_DIM / 4;
        split_kernel<<<(n4 + 255) / 256, 256>>>(batch, a_hi, a_lo, n4);
        transpose_split_kernel<<<dim3(H_DIM / 32, D_DIM / 32), dim3(32, 8)>>>(
            W1, w1t_hi, w1t_lo, D_DIM, H_DIM);
        transpose_split_kernel<<<dim3(R_DIM / 32, H_DIM / 32), dim3(32, 8)>>>(
            W2, w2t_hi, w2t_lo, H_DIM, R_DIM);
    }
    // 1) h = relu(batch @ W1 + b1) -> bf16 hi/lo
    {
        dim3 grid(H_DIM / 128, M_TOT / 128);   // (8, 128)
        mma_gemm<0><<<grid, 256, MMA_SMEM>>>(
            a_hi, a_lo, w1t_hi, w1t_lo, b1, nullptr, h_hi, h_lo, D_DIM, H_DIM);
    }
    // 2) t = relu(h @ W2 + b2) -> bf16 hi/lo + per-row squared norms
    {
        dim3 grid(R_DIM / 128, M_TOT / 128);   // (1, 128)
        mma_gemm<1><<<grid, 256, MMA_SMEM>>>(
            h_hi, h_lo, w2t_hi, w2t_lo, b2, sq_ptr, t_hi, t_lo, H_DIM, R_DIM);
    }
    // 3) pairwise distances: out[b,i,j] = max(sq_i + sq_j - 2 t_i.t_j, 0)
    {
        dim3 grid(L_DIM / 128, L_DIM / 128, B_DIM);   // (8, 8, 16)
        mma_gemm<2><<<grid, 256, MMA_SMEM>>>(
            t_hi, t_lo, t_hi, t_lo, sq_ptr, out, nullptr, nullptr, R_DIM, L_DIM);
    }
}

// round 5
// speedup vs baseline: 2.7808x; 1.0902x over previous
#include <cuda_runtime.h>
#include <cuda_bf16.h>
#include <cstdint>
#include <cstddef>

// Shapes: batch[16,1024,1024] -> M=16384,K=1024 ; W1[1024,1024] ; W2[1024,128]
// out[16,1024,1024] fp32.
static const int M_TOT = 16384;
static const int D_DIM = 1024;
static const int H_DIM = 1024;
static const int R_DIM = 128;
static const int L_DIM = 1024;
static const int B_DIM = 16;

// ---- scratch (__device__ globals; no runtime allocation allowed) ----
__device__ __align__(256) __nv_bfloat16 g_a_hi[(size_t)16384 * 1024];
__device__ __align__(256) __nv_bfloat16 g_a_lo[(size_t)16384 * 1024];
__device__ __align__(256) __nv_bfloat16 g_h_hi[(size_t)16384 * 1024];
__device__ __align__(256) __nv_bfloat16 g_h_lo[(size_t)16384 * 1024];
__device__ __align__(256) __nv_bfloat16 g_w1t_hi[(size_t)1024 * 1024];
__device__ __align__(256) __nv_bfloat16 g_w1t_lo[(size_t)1024 * 1024];
__device__ __align__(256) __nv_bfloat16 g_w2t_hi[(size_t)128 * 1024];
__device__ __align__(256) __nv_bfloat16 g_w2t_lo[(size_t)128 * 1024];
__device__ __align__(256) __nv_bfloat16 g_t_hi[(size_t)16384 * 128];
__device__ __align__(256) __nv_bfloat16 g_t_lo[(size_t)16384 * 128];
__device__ __align__(256) float g_sq[16384];

// ---------------- PTX helpers (sm_80-era only: ldmatrix / mma.sync / cp.async) ----
__device__ __forceinline__ uint32_t smem_u32(const void* p) {
    uint32_t a;
    asm("{ .reg .u64 t; cvta.to.shared.u64 t, %1; cvt.u32.u64 %0, t; }" : "=r"(a) : "l"(p));
    return a;
}
__device__ __forceinline__ void cp16(uint32_t saddr, const void* g) {
    asm volatile("cp.async.cg.shared.global [%0], [%1], 16;" :: "r"(saddr), "l"(g));
}
__device__ __forceinline__ void cp_commit() {
    asm volatile("cp.async.commit_group;" ::: "memory");
}
__device__ __forceinline__ void cp_wait1() {
    asm volatile("cp.async.wait_group 1;" ::: "memory");
}
__device__ __forceinline__ void ldsm4(uint32_t* r, uint32_t addr) {
    asm volatile("ldmatrix.sync.aligned.m8n8.x4.shared.b16 {%0,%1,%2,%3}, [%4];"
                 : "=r"(r[0]), "=r"(r[1]), "=r"(r[2]), "=r"(r[3]) : "r"(addr));
}
__device__ __forceinline__ void mma_bf16(float* c, const uint32_t* a, const uint32_t* b) {
    asm volatile(
        "mma.sync.aligned.m16n8k16.row.col.f32.bf16.bf16.f32 "
        "{%0,%1,%2,%3}, {%4,%5,%6,%7}, {%8,%9}, {%0,%1,%2,%3};"
        : "+f"(c[0]), "+f"(c[1]), "+f"(c[2]), "+f"(c[3])
        : "r"(a[0]), "r"(a[1]), "r"(a[2]), "r"(a[3]), "r"(b[0]), "r"(b[1]));
}

// ---------------- unified tensor-core GEMM via mma.sync ------------------------
// acc = A @ B^T with split bf16 operands (hi/lo, 3 products, fp32 accumulate).
// MODE 0 (GEMM1): C = relu(acc + bias) -> bf16 hi/lo pair (Chi/Clo)
// MODE 1 (GEMM2): C = relu(acc + bias) -> bf16 hi/lo pair + per-row sumsq -> Cf(=g_sq)
// MODE 2 (DIST):  per-batch z: out = max(sq[i] + sq[j] - 2*acc, 0) -> Cf; bias = sq
// Tiles: BM=128, BN=128, BK=32. 8 warps: warp_m=wid&3 (32 rows), warp_n=wid>>2 (64 cols).
//
// smem: 3 stages x 32KB. Each stage: A tile 128 rows x 128B [hi 64B | lo 64B],
// then B tile likewise at +16384. SW128-style swizzle: 16B chunk c of row r is
// stored at chunk (c ^ (r & 7)) -> conflict-free ldmatrix + cp.async.
static const int STAGE = 32768;
static const int MMA_SMEM = 3 * STAGE + 512;   // + per-row sq scratch (MODE 1)

template <int MODE>
__global__ __launch_bounds__(256, 2)
void mma_gemm(const __nv_bfloat16* __restrict__ Ahi, const __nv_bfloat16* __restrict__ Alo,
              const __nv_bfloat16* __restrict__ Bhi, const __nv_bfloat16* __restrict__ Blo,
              const float* __restrict__ bias,
              float* __restrict__ Cf,
              __nv_bfloat16* __restrict__ Chi, __nv_bfloat16* __restrict__ Clo,
              int K, int Ncols) {
    extern __shared__ char smem[];
    const uint32_t sbase = smem_u32(smem);
    float* sq_s = reinterpret_cast<float*>(smem + 3 * STAGE);
    const int tid = threadIdx.x;
    const int lane = tid & 31;
    const int wid = tid >> 5;
    const int warp_m = wid & 3;
    const int warp_n = wid >> 2;

    const int mBase = blockIdx.y * 128;
    const int nBase = blockIdx.x * 128;
    const int zb = (MODE == 2) ? blockIdx.z : 0;
    const size_t zrow = (size_t)zb * 1024;     // row offset into A/B for batched dist
    const int NC = K >> 5;                     // chunks of 32

    if (MODE == 1 && tid < 128) sq_s[tid] = 0.0f;

    float acc[2][8][4];
#pragma unroll
    for (int i = 0; i < 2; i++)
#pragma unroll
        for (int j = 0; j < 8; j++)
#pragma unroll
            for (int q = 0; q < 4; q++) acc[i][j][q] = 0.0f;

    // Loader: 2048 16B-chunks per stage (A:1024, B:1024), 8 per thread.
    // id = tid + it*256: it<4 -> A, it>=4 -> B (compile-time split).
    auto load_chunk = [&](int c, int stg) {
        const int k0 = c << 5;
        const uint32_t sb = sbase + stg * STAGE;
#pragma unroll
        for (int it = 0; it < 8; ++it) {
            const int id = tid + it * 256;
            const bool isB = (it >= 4);
            const int l2 = id & 1023;
            const int row = l2 >> 3;
            const int half = (l2 >> 2) & 1;    // 0=hi, 1=lo
            const int sub = l2 & 3;            // 16B sub-chunk within 64B
            const int chunk = half * 4 + sub;  // logical 16B chunk 0..7
            const __nv_bfloat16* src =
                isB ? (half ? Blo : Bhi) : (half ? Alo : Ahi);
            const size_t goff =
                (zrow + (isB ? nBase : mBase) + row) * (size_t)K + k0 + sub * 8;
            const uint32_t dst = sb + (isB ? 16384 : 0) + row * 128 +
                                 (((chunk ^ (row & 7))) << 4);
            cp16(dst, src + goff);
        }
    };

    load_chunk(0, 0); cp_commit();
    if (NC > 1) load_chunk(1, 1);
    cp_commit();

    // ldmatrix lane-address components
    const int a_row_base = warp_m * 32 + (lane & 15);
    const int a_csel = lane >> 4;                          // 0/1 (k 0/8)
    const int a_rx = a_row_base & 7;                       // invariant over mi (+16)
    const int b_row_base = warp_n * 64 + (lane & 7) + ((lane >> 4) << 3);
    const int b_csel = (lane >> 3) & 1;                    // k 0/8
    const int b_rx = b_row_base & 7;                       // invariant over np (+16)

    int stg_r = 0, stg_w = 2;
    for (int c = 0; c < NC; ++c) {
        cp_wait1();
        __syncthreads();
        if (c + 2 < NC) load_chunk(c + 2, stg_w);
        cp_commit();
        const uint32_t base = sbase + stg_r * STAGE;
#pragma unroll
        for (int ks = 0; ks < 2; ++ks) {
            uint32_t Ah[2][4], Al[2][4];
#pragma unroll
            for (int mi = 0; mi < 2; ++mi) {
                const int row = a_row_base + mi * 16;
                const uint32_t rb = base + row * 128;
                ldsm4(Ah[mi], rb + (((ks * 2 + a_csel) ^ a_rx) << 4));
                ldsm4(Al[mi], rb + (((4 + ks * 2 + a_csel) ^ a_rx) << 4));
            }
#pragma unroll
            for (int np = 0; np < 4; ++np) {
                uint32_t Bh[4], Bl[4];
                const int n = b_row_base + np * 16;
                const uint32_t rb = base + 16384 + n * 128;
                ldsm4(Bh, rb + (((ks * 2 + b_csel) ^ b_rx) << 4));
                ldsm4(Bl, rb + (((4 + ks * 2 + b_csel) ^ b_rx) << 4));
#pragma unroll
                for (int half = 0; half < 2; ++half) {
                    const uint32_t bh[2] = {Bh[half * 2], Bh[half * 2 + 1]};
                    const uint32_t bl[2] = {Bl[half * 2], Bl[half * 2 + 1]};
#pragma unroll
                    for (int mi = 0; mi < 2; ++mi) {
                        float* cc = acc[mi][np * 2 + half];
                        mma_bf16(cc, Ah[mi], bh);
                        mma_bf16(cc, Ah[mi], bl);
                        mma_bf16(cc, Al[mi], bh);
                    }
                }
            }
        }
        if (++stg_r == 3) stg_r = 0;
        if (++stg_w == 3) stg_w = 0;
    }

    // ---------------- epilogue ----------------
    if (MODE == 2) {
        const float* sqg = bias + zb * 1024;
        float* Ob = Cf + (size_t)zb * 1024 * 1024;
#pragma unroll
        for (int mi = 0; mi < 2; ++mi) {
            const int r0 = mBase + warp_m * 32 + mi * 16 + (lane >> 2);
            const float sr0 = sqg[r0], sr1 = sqg[r0 + 8];
#pragma unroll
            for (int ni = 0; ni < 8; ++ni) {
                const int col = nBase + warp_n * 64 + ni * 8 + 2 * (lane & 3);
                const float sc0 = sqg[col], sc1 = sqg[col + 1];
                const float* cc = acc[mi][ni];
                *reinterpret_cast<float2*>(Ob + (size_t)r0 * Ncols + col) =
                    make_float2(fmaxf(sr0 + sc0 - 2.0f * cc[0], 0.f),
                                fmaxf(sr0 + sc1 - 2.0f * cc[1], 0.f));
                *reinterpret_cast<float2*>(Ob + (size_t)(r0 + 8) * Ncols + col) =
                    make_float2(fmaxf(sr1 + sc0 - 2.0f * cc[2], 0.f),
                                fmaxf(sr1 + sc1 - 2.0f * cc[3], 0.f));
            }
        }
    } else {
#pragma unroll
        for (int mi = 0; mi < 2; ++mi) {
            const int r0 = mBase + warp_m * 32 + mi * 16 + (lane >> 2);
            float ss0 = 0.0f, ss1 = 0.0f;
#pragma unroll
            for (int ni = 0; ni < 8; ++ni) {
                const int col = nBase + warp_n * 64 + ni * 8 + 2 * (lane & 3);
                const float bz0 = bias[col], bz1 = bias[col + 1];
                const float* cc = acc[mi][ni];
                const float v00 = fmaxf(cc[0] + bz0, 0.f), v01 = fmaxf(cc[1] + bz1, 0.f);
                const float v10 = fmaxf(cc[2] + bz0, 0.f), v11 = fmaxf(cc[3] + bz1, 0.f);
                if (MODE == 1) { ss0 += v00 * v00 + v01 * v01; ss1 += v10 * v10 + v11 * v11; }
                __nv_bfloat16 h00 = __float2bfloat16(v00), h01 = __float2bfloat16(v01);
                __nv_bfloat16 h10 = __float2bfloat16(v10), h11 = __float2bfloat16(v11);
                __nv_bfloat16 l00 = __float2bfloat16(v00 - __bfloat162float(h00));
                __nv_bfloat16 l01 = __float2bfloat16(v01 - __bfloat162float(h01));
                __nv_bfloat16 l10 = __float2bfloat16(v10 - __bfloat162float(h10));
                __nv_bfloat16 l11 = __float2bfloat16(v11 - __bfloat162float(h11));
                __nv_bfloat162 hp0 = __halves2bfloat162(h00, h01);
                __nv_bfloat162 hp1 = __halves2bfloat162(h10, h11);
                __nv_bfloat162 lp0 = __halves2bfloat162(l00, l01);
                __nv_bfloat162 lp1 = __halves2bfloat162(l10, l11);
                *reinterpret_cast<uint32_t*>(Chi + (size_t)r0 * Ncols + col) =
                    *reinterpret_cast<uint32_t*>(&hp0);
                *reinterpret_cast<uint32_t*>(Chi + (size_t)(r0 + 8) * Ncols + col) =
                    *reinterpret_cast<uint32_t*>(&hp1);
                *reinterpret_cast<uint32_t*>(Clo + (size_t)r0 * Ncols + col) =
                    *reinterpret_cast<uint32_t*>(&lp0);
                *reinterpret_cast<uint32_t*>(Clo + (size_t)(r0 + 8) * Ncols + col) =
                    *reinterpret_cast<uint32_t*>(&lp1);
            }
            if (MODE == 1) {
                atomicAdd(&sq_s[r0 - mBase], ss0);
                atomicAdd(&sq_s[r0 + 8 - mBase], ss1);
            }
        }
        if (MODE == 1) {
            __syncthreads();
            if (tid < 128) Cf[mBase + tid] = sq_s[tid];
        }
    }
}

// ---------------- conversion kernels ----------------
__global__ void split_kernel(const float* __restrict__ x,
                             __nv_bfloat16* __restrict__ hi,
                             __nv_bfloat16* __restrict__ lo, int n4) {
    int i = blockIdx.x * 256 + threadIdx.x;
    if (i >= n4) return;
    float4 v = reinterpret_cast<const float4*>(x)[i];
    __nv_bfloat16 h0 = __float2bfloat16(v.x), h1 = __float2bfloat16(v.y);
    __nv_bfloat16 h2 = __float2bfloat16(v.z), h3 = __float2bfloat16(v.w);
    __nv_bfloat16 l0 = __float2bfloat16(v.x - __bfloat162float(h0));
    __nv_bfloat16 l1 = __float2bfloat16(v.y - __bfloat162float(h1));
    __nv_bfloat16 l2 = __float2bfloat16(v.z - __bfloat162float(h2));
    __nv_bfloat16 l3 = __float2bfloat16(v.w - __bfloat162float(h3));
    __nv_bfloat162 hp0 = __halves2bfloat162(h0, h1), hp1 = __halves2bfloat162(h2, h3);
    __nv_bfloat162 lp0 = __halves2bfloat162(l0, l1), lp1 = __halves2bfloat162(l2, l3);
    reinterpret_cast<uint2*>(hi)[i] =
        make_uint2(*reinterpret_cast<uint32_t*>(&hp0), *reinterpret_cast<uint32_t*>(&hp1));
    reinterpret_cast<uint2*>(lo)[i] =
        make_uint2(*reinterpret_cast<uint32_t*>(&lp0), *reinterpret_cast<uint32_t*>(&lp1));
}

// W[K,N] fp32 -> Wt_hi/lo[N,K] bf16 (transposed split), 32x32 smem tiles.
__global__ void transpose_split_kernel(const float* __restrict__ W,
                                       __nv_bfloat16* __restrict__ th,
                                       __nv_bfloat16* __restrict__ tl, int K, int N) {
    __shared__ float tile[32][33];
    const int kb = blockIdx.y * 32;
    const int nb = blockIdx.x * 32;
    const int tx = threadIdx.x, ty = threadIdx.y;   // block (32, 8)
#pragma unroll
    for (int i = 0; i < 4; ++i)
        tile[ty + i * 8][tx] = W[(size_t)(kb + ty + i * 8) * N + nb + tx];
    __syncthreads();
#pragma unroll
    for (int i = 0; i < 4; ++i) {
        const int n = nb + ty + i * 8;
        const int k = kb + tx;
        const float v = tile[tx][ty + i * 8];
        __nv_bfloat16 h = __float2bfloat16(v);
        th[(size_t)n * K + k] = h;
        tl[(size_t)n * K + k] = __float2bfloat16(v - __bfloat162float(h));
    }
}

// ---------------------------------------------------------------------------
extern "C" void kernel_launch(void* const* d_in, const int* in_sizes, int n_in,
                              void* d_out, int out_size) {
    const float* batch = (const float*)d_in[0];
    const float* W1    = (const float*)d_in[1];
    const float* b1    = (const float*)d_in[2];
    const float* W2    = (const float*)d_in[3];
    const float* b2    = (const float*)d_in[4];
    float* out = (float*)d_out;

    __nv_bfloat16 *a_hi, *a_lo, *h_hi, *h_lo, *w1t_hi, *w1t_lo, *w2t_hi, *w2t_lo, *t_hi, *t_lo;
    float *sq_ptr;
    cudaGetSymbolAddress((void**)&a_hi,   g_a_hi);
    cudaGetSymbolAddress((void**)&a_lo,   g_a_lo);
    cudaGetSymbolAddress((void**)&h_hi,   g_h_hi);
    cudaGetSymbolAddress((void**)&h_lo,   g_h_lo);
    cudaGetSymbolAddress((void**)&w1t_hi, g_w1t_hi);
    cudaGetSymbolAddress((void**)&w1t_lo, g_w1t_lo);
    cudaGetSymbolAddress((void**)&w2t_hi, g_w2t_hi);
    cudaGetSymbolAddress((void**)&w2t_lo, g_w2t_lo);
    cudaGetSymbolAddress((void**)&t_hi,   g_t_hi);
    cudaGetSymbolAddress((void**)&t_lo,   g_t_lo);
    cudaGetSymbolAddress((void**)&sq_ptr, g_sq);

    cudaFuncSetAttribute(mma_gemm<0>, cudaFuncAttributeMaxDynamicSharedMemorySize, MMA_SMEM);
    cudaFuncSetAttribute(mma_gemm<1>, cudaFuncAttributeMaxDynamicSharedMemorySize, MMA_SMEM);
    cudaFuncSetAttribute(mma_gemm<2>, cudaFuncAttributeMaxDynamicSharedMemorySize, MMA_SMEM);

    // 0) precision splits
    {
        int n4 = M_TOT * D_DIM / 4;
        split_kernel<<<(n4 + 255) / 256, 256>>>(batch, a_hi, a_lo, n4);
        transpose_split_kernel<<<dim3(H_DIM / 32, D_DIM / 32), dim3(32, 8)>>>(
            W1, w1t_hi, w1t_lo, D_DIM, H_DIM);
        transpose_split_kernel<<<dim3(R_DIM / 32, H_DIM / 32), dim3(32, 8)>>>(
            W2, w2t_hi, w2t_lo, H_DIM, R_DIM);
    }
    // 1) h = relu(batch @ W1 + b1) -> bf16 hi/lo
    {
        dim3 grid(H_DIM / 128, M_TOT / 128);   // (8, 128)
        mma_gemm<0><<<grid, 256, MMA_SMEM>>>(
            a_hi, a_lo, w1t_hi, w1t_lo, b1, nullptr, h_hi, h_lo, D_DIM, H_DIM);
    }
    // 2) t = relu(h @ W2 + b2) -> bf16 hi/lo + per-row squared norms
    {
        dim3 grid(R_DIM / 128, M_TOT / 128);   // (1, 128)
        mma_gemm<1><<<grid, 256, MMA_SMEM>>>(
            h_hi, h_lo, w2t_hi, w2t_lo, b2, sq_ptr, t_hi, t_lo, H_DIM, R_DIM);
    }
    // 3) pairwise distances: out[b,i,j] = max(sq_i + sq_j - 2 t_i.t_j, 0)
    {
        dim3 grid(L_DIM / 128, L_DIM / 128, B_DIM);   // (8, 8, 16)
        mma_gemm<2><<<grid, 256, MMA_SMEM>>>(
            t_hi, t_lo, t_hi, t_lo, sq_ptr, out, nullptr, nullptr, R_DIM, L_DIM);
    }
}

// round 6
// speedup vs baseline: 3.6650x; 1.3180x over previous
#include <cuda_runtime.h>
#include <cuda_fp16.h>
#include <cstdint>
#include <cstddef>

// Shapes: batch[16,1024,1024] -> M=16384,K=1024 ; W1[1024,1024] ; W2[1024,128]
// out[16,1024,1024] fp32.
static const int M_TOT = 16384;
static const int D_DIM = 1024;
static const int H_DIM = 1024;
static const int R_DIM = 128;
static const int L_DIM = 1024;
static const int B_DIM = 16;

// ---- scratch (__device__ globals; no runtime allocation allowed) ----
// fp16 two-product scheme: activations need hi only; weights + t need hi/lo.
__device__ __align__(256) __half g_a_hi[(size_t)16384 * 1024];
__device__ __align__(256) __half g_h_hi[(size_t)16384 * 1024];
__device__ __align__(256) __half g_w1t_hi[(size_t)1024 * 1024];
__device__ __align__(256) __half g_w1t_lo[(size_t)1024 * 1024];
__device__ __align__(256) __half g_w2t_hi[(size_t)128 * 1024];
__device__ __align__(256) __half g_w2t_lo[(size_t)128 * 1024];
__device__ __align__(256) __half g_t_hi[(size_t)16384 * 128];
__device__ __align__(256) __half g_t_lo[(size_t)16384 * 128];
__device__ __align__(256) float g_sq[16384];

// ---------------- PTX helpers ----------------
__device__ __forceinline__ uint32_t smem_u32(const void* p) {
    uint32_t a;
    asm("{ .reg .u64 t; cvta.to.shared.u64 t, %1; cvt.u32.u64 %0, t; }" : "=r"(a) : "l"(p));
    return a;
}
__device__ __forceinline__ void cp16(uint32_t saddr, const void* g) {
    asm volatile("cp.async.cg.shared.global [%0], [%1], 16;" :: "r"(saddr), "l"(g));
}
__device__ __forceinline__ void cp_commit() {
    asm volatile("cp.async.commit_group;" ::: "memory");
}
__device__ __forceinline__ void ldsm4(uint32_t* r, uint32_t addr) {
    asm volatile("ldmatrix.sync.aligned.m8n8.x4.shared.b16 {%0,%1,%2,%3}, [%4];"
                 : "=r"(r[0]), "=r"(r[1]), "=r"(r[2]), "=r"(r[3]) : "r"(addr));
}
__device__ __forceinline__ void mma_f16(float* c, const uint32_t* a, const uint32_t* b) {
    asm volatile(
        "mma.sync.aligned.m16n8k16.row.col.f32.f16.f16.f32 "
        "{%0,%1,%2,%3}, {%4,%5,%6,%7}, {%8,%9}, {%0,%1,%2,%3};"
        : "+f"(c[0]), "+f"(c[1]), "+f"(c[2]), "+f"(c[3])
        : "r"(a[0]), "r"(a[1]), "r"(a[2]), "r"(a[3]), "r"(b[0]), "r"(b[1]));
}

// ---------------- unified tensor-core GEMM ------------------------
// acc = A @ B^T, fp16 split operands.
// MODE 0 (GEMM1): 2 products (Ah*Bh + Ah*Bl); C = relu(acc+bias) -> half hi only
// MODE 1 (GEMM2): 2 products; C -> half hi/lo + per-row sumsq -> Cf(=g_sq)
// MODE 2 (DIST):  3 products (+Al*Bh); out = max(sq_i+sq_j-2*acc, 0); bias = sq
// CTA tile 128x128, BK=32. 8 warps as 2(m) x 4(n); warp tile 64x32.
//
// smem stage: A-hi 8KB [+ A-lo 8KB in MODE2], B-hi 8KB, B-lo 8KB.
// Rows are 64B (32 fp16 of the k-chunk); 16B chunk sub of row r stored at
// sub' = (sub + (r>>1)) & 3  -> conflict-free for cp.async stores + ldmatrix.
template <int MODE>
__global__ __launch_bounds__(256, 2)
void mma_gemm(const __half* __restrict__ Ahi, const __half* __restrict__ Alo,
              const __half* __restrict__ Bhi, const __half* __restrict__ Blo,
              const float* __restrict__ bias,
              float* __restrict__ Cf,
              __half* __restrict__ Chi, __half* __restrict__ Clo,
              int K, int Ncols) {
    constexpr int NSTG = (MODE == 2) ? 3 : 4;
    constexpr int ASZ  = (MODE == 2) ? 16384 : 8192;
    constexpr int STG  = ASZ + 16384;
    constexpr int NITER = STG / 16 / 256;          // 6 or 8
    constexpr bool PROD3 = (MODE == 2);

    extern __shared__ char smem[];
    const uint32_t sbase = smem_u32(smem);
    float* sq_s = reinterpret_cast<float*>(smem + NSTG * STG);
    const int tid = threadIdx.x;
    const int lane = tid & 31;
    const int wid = tid >> 5;
    const int warp_m = wid & 1;       // 2 m-warps
    const int warp_n = wid >> 1;      // 4 n-warps

    const int mBase = blockIdx.y * 128;
    const int nBase = blockIdx.x * 128;
    const int zb = (MODE == 2) ? blockIdx.z : 0;
    const size_t zrow = (size_t)zb * 1024;
    const int NC = K >> 5;

    if (MODE == 1 && tid < 128) sq_s[tid] = 0.0f;

    float acc[4][4][4];
#pragma unroll
    for (int i = 0; i < 4; i++)
#pragma unroll
        for (int j = 0; j < 4; j++)
#pragma unroll
            for (int q = 0; q < 4; q++) acc[i][j][q] = 0.0f;

    // Loader: NITER*256 16B chunks per stage. seg = it>>1 (constant per it).
    auto load_chunk = [&](int c, int stg) {
        const int k0 = c << 5;
        const uint32_t sb = sbase + stg * STG;
#pragma unroll
        for (int it = 0; it < NITER; ++it) {
            const int seg = it >> 1;               // compile-time per it
            const int l = (tid + it * 256) & 511;
            const int row = l >> 2;
            const int sub = l & 3;
            const __half* src;
            uint32_t soff;
            int rb;
            if (MODE == 2) {
                // segs: 0=A-hi 1=A-lo 2=B-hi 3=B-lo
                src = (seg == 0) ? Ahi : (seg == 1) ? Alo : (seg == 2) ? Bhi : Blo;
                soff = (uint32_t)seg * 8192u;
                rb = (seg < 2) ? mBase : nBase;
            } else {
                // segs: 0=A-hi 1=B-hi 2=B-lo
                src = (seg == 0) ? Ahi : (seg == 1) ? Bhi : Blo;
                soff = (seg == 0) ? 0u : (seg == 1) ? (uint32_t)ASZ : (uint32_t)ASZ + 8192u;
                rb = (seg == 0) ? mBase : nBase;
            }
            const size_t goff = (zrow + rb + row) * (size_t)K + k0 + sub * 8;
            const uint32_t dst = sb + soff + row * 64 + (((sub + (row >> 1)) & 3) << 4);
            cp16(dst, src + goff);
        }
    };

    load_chunk(0, 0); cp_commit();
#pragma unroll
    for (int s = 1; s < NSTG; ++s) {
        if (s < NC) load_chunk(s, s);
        cp_commit();
    }

    // ldmatrix per-lane components (swizzle base is fragment-invariant)
    const int a_row_l = lane & 15;
    const int a_sw = (lane >> 4) + (a_row_l >> 1);       // + ks*2, &3
    const int b_row_l = (lane & 7) + ((lane >> 4) << 3);
    const int b_sw = ((lane >> 3) & 1) + (b_row_l >> 1);

    for (int c = 0; c < NC; ++c) {
        if (NSTG == 4) asm volatile("cp.async.wait_group 2;" ::: "memory");
        else           asm volatile("cp.async.wait_group 1;" ::: "memory");
        __syncthreads();
        if (c + NSTG - 1 < NC) load_chunk(c + NSTG - 1, (c + NSTG - 1) % NSTG);
        cp_commit();
        const uint32_t base = sbase + (c % NSTG) * STG;
#pragma unroll
        for (int ks = 0; ks < 2; ++ks) {
            uint32_t Ah[4][4], Al[4][4];
#pragma unroll
            for (int mi = 0; mi < 4; ++mi) {
                const int row = warp_m * 64 + mi * 16 + a_row_l;
                const uint32_t addr =
                    base + row * 64 + (((ks * 2 + a_sw) & 3) << 4);
                ldsm4(Ah[mi], addr);
                if (PROD3) ldsm4(Al[mi], addr + 8192);
            }
#pragma unroll
            for (int np = 0; np < 2; ++np) {
                uint32_t Bh[4], Bl[4];
                const int n = warp_n * 32 + np * 16 + b_row_l;
                const uint32_t baddr =
                    base + ASZ + n * 64 + (((ks * 2 + b_sw) & 3) << 4);
                ldsm4(Bh, baddr);
                ldsm4(Bl, baddr + 8192);
#pragma unroll
                for (int half = 0; half < 2; ++half) {
                    const uint32_t bh[2] = {Bh[half * 2], Bh[half * 2 + 1]};
                    const uint32_t bl[2] = {Bl[half * 2], Bl[half * 2 + 1]};
#pragma unroll
                    for (int mi = 0; mi < 4; ++mi) {
                        float* cc = acc[mi][np * 2 + half];
                        mma_f16(cc, Ah[mi], bh);
                        mma_f16(cc, Ah[mi], bl);
                        if (PROD3) mma_f16(cc, Al[mi], bh);
                    }
                }
            }
        }
    }

    // ---------------- epilogue ----------------
    if (MODE == 2) {
        const float* sqg = bias + zb * 1024;
        float* Ob = Cf + (size_t)zb * 1024 * 1024;
#pragma unroll
        for (int mi = 0; mi < 4; ++mi) {
            const int r0 = mBase + warp_m * 64 + mi * 16 + (lane >> 2);
            const float sr0 = sqg[r0], sr1 = sqg[r0 + 8];
#pragma unroll
            for (int ni = 0; ni < 4; ++ni) {
                const int col = nBase + warp_n * 32 + ni * 8 + 2 * (lane & 3);
                const float sc0 = sqg[col], sc1 = sqg[col + 1];
                const float* cc = acc[mi][ni];
                *reinterpret_cast<float2*>(Ob + (size_t)r0 * Ncols + col) =
                    make_float2(fmaxf(sr0 + sc0 - 2.0f * cc[0], 0.f),
                                fmaxf(sr0 + sc1 - 2.0f * cc[1], 0.f));
                *reinterpret_cast<float2*>(Ob + (size_t)(r0 + 8) * Ncols + col) =
                    make_float2(fmaxf(sr1 + sc0 - 2.0f * cc[2], 0.f),
                                fmaxf(sr1 + sc1 - 2.0f * cc[3], 0.f));
            }
        }
    } else {
#pragma unroll
        for (int mi = 0; mi < 4; ++mi) {
            const int r0 = mBase + warp_m * 64 + mi * 16 + (lane >> 2);
            float ss0 = 0.0f, ss1 = 0.0f;
#pragma unroll
            for (int ni = 0; ni < 4; ++ni) {
                const int col = nBase + warp_n * 32 + ni * 8 + 2 * (lane & 3);
                const float bz0 = __ldg(&bias[col]), bz1 = __ldg(&bias[col + 1]);
                const float* cc = acc[mi][ni];
                const float v00 = fmaxf(cc[0] + bz0, 0.f), v01 = fmaxf(cc[1] + bz1, 0.f);
                const float v10 = fmaxf(cc[2] + bz0, 0.f), v11 = fmaxf(cc[3] + bz1, 0.f);
                if (MODE == 1) { ss0 += v00 * v00 + v01 * v01; ss1 += v10 * v10 + v11 * v11; }
                const __half h00 = __float2half_rn(v00), h01 = __float2half_rn(v01);
                const __half h10 = __float2half_rn(v10), h11 = __float2half_rn(v11);
                __half2 hp0 = __halves2half2(h00, h01);
                __half2 hp1 = __halves2half2(h10, h11);
                *reinterpret_cast<uint32_t*>(Chi + (size_t)r0 * Ncols + col) =
                    *reinterpret_cast<uint32_t*>(&hp0);
                *reinterpret_cast<uint32_t*>(Chi + (size_t)(r0 + 8) * Ncols + col) =
                    *reinterpret_cast<uint32_t*>(&hp1);
                if (MODE == 1) {
                    const __half l00 = __float2half_rn(v00 - __half2float(h00));
                    const __half l01 = __float2half_rn(v01 - __half2float(h01));
                    const __half l10 = __float2half_rn(v10 - __half2float(h10));
                    const __half l11 = __float2half_rn(v11 - __half2float(h11));
                    __half2 lp0 = __halves2half2(l00, l01);
                    __half2 lp1 = __halves2half2(l10, l11);
                    *reinterpret_cast<uint32_t*>(Clo + (size_t)r0 * Ncols + col) =
                        *reinterpret_cast<uint32_t*>(&lp0);
                    *reinterpret_cast<uint32_t*>(Clo + (size_t)(r0 + 8) * Ncols + col) =
                        *reinterpret_cast<uint32_t*>(&lp1);
                }
            }
            if (MODE == 1) {
                atomicAdd(&sq_s[r0 - mBase], ss0);
                atomicAdd(&sq_s[r0 + 8 - mBase], ss1);
            }
        }
        if (MODE == 1) {
            __syncthreads();
            if (tid < 128) Cf[mBase + tid] = sq_s[tid];
        }
    }
}

static const int MMA_SMEM = 98304 + 512;   // 4*24576 (or 3*32768) + sq scratch

// ---------------- conversion kernels ----------------
// fp32 -> fp16 hi only (activations)
__global__ void split_hi_kernel(const float* __restrict__ x,
                                __half* __restrict__ hi, int n4) {
    int i = blockIdx.x * 256 + threadIdx.x;
    if (i >= n4) return;
    float4 v = reinterpret_cast<const float4*>(x)[i];
    __half2 h0 = __halves2half2(__float2half_rn(v.x), __float2half_rn(v.y));
    __half2 h1 = __halves2half2(__float2half_rn(v.z), __float2half_rn(v.w));
    reinterpret_cast<uint2*>(hi)[i] =
        make_uint2(*reinterpret_cast<uint32_t*>(&h0), *reinterpret_cast<uint32_t*>(&h1));
}

// W[K,N] fp32 -> Wt hi/lo fp16 [N,K] (transposed split), 32x32 smem tiles.
__global__ void transpose_split_kernel(const float* __restrict__ W,
                                       __half* __restrict__ th,
                                       __half* __restrict__ tl, int K, int N) {
    __shared__ float tile[32][33];
    const int kb = blockIdx.y * 32;
    const int nb = blockIdx.x * 32;
    const int tx = threadIdx.x, ty = threadIdx.y;   // block (32, 8)
#pragma unroll
    for (int i = 0; i < 4; ++i)
        tile[ty + i * 8][tx] = W[(size_t)(kb + ty + i * 8) * N + nb + tx];
    __syncthreads();
#pragma unroll
    for (int i = 0; i < 4; ++i) {
        const int n = nb + ty + i * 8;
        const int k = kb + tx;
        const float v = tile[tx][ty + i * 8];
        const __half h = __float2half_rn(v);
        th[(size_t)n * K + k] = h;
        tl[(size_t)n * K + k] = __float2half_rn(v - __half2float(h));
    }
}

// ---------------------------------------------------------------------------
extern "C" void kernel_launch(void* const* d_in, const int* in_sizes, int n_in,
                              void* d_out, int out_size) {
    const float* batch = (const float*)d_in[0];
    const float* W1    = (const float*)d_in[1];
    const float* b1    = (const float*)d_in[2];
    const float* W2    = (const float*)d_in[3];
    const float* b2    = (const float*)d_in[4];
    float* out = (float*)d_out;

    __half *a_hi, *h_hi, *w1t_hi, *w1t_lo, *w2t_hi, *w2t_lo, *t_hi, *t_lo;
    float *sq_ptr;
    cudaGetSymbolAddress((void**)&a_hi,   g_a_hi);
    cudaGetSymbolAddress((void**)&h_hi,   g_h_hi);
    cudaGetSymbolAddress((void**)&w1t_hi, g_w1t_hi);
    cudaGetSymbolAddress((void**)&w1t_lo, g_w1t_lo);
    cudaGetSymbolAddress((void**)&w2t_hi, g_w2t_hi);
    cudaGetSymbolAddress((void**)&w2t_lo, g_w2t_lo);
    cudaGetSymbolAddress((void**)&t_hi,   g_t_hi);
    cudaGetSymbolAddress((void**)&t_lo,   g_t_lo);
    cudaGetSymbolAddress((void**)&sq_ptr, g_sq);

    cudaFuncSetAttribute(mma_gemm<0>, cudaFuncAttributeMaxDynamicSharedMemorySize, MMA_SMEM);
    cudaFuncSetAttribute(mma_gemm<1>, cudaFuncAttributeMaxDynamicSharedMemorySize, MMA_SMEM);
    cudaFuncSetAttribute(mma_gemm<2>, cudaFuncAttributeMaxDynamicSharedMemorySize, MMA_SMEM);

    // 0) precision splits
    {
        int n4 = M_TOT * D_DIM / 4;
        split_hi_kernel<<<(n4 + 255) / 256, 256>>>(batch, a_hi, n4);
        transpose_split_kernel<<<dim3(H_DIM / 32, D_DIM / 32), dim3(32, 8)>>>(
            W1, w1t_hi, w1t_lo, D_DIM, H_DIM);
        transpose_split_kernel<<<dim3(R_DIM / 32, H_DIM / 32), dim3(32, 8)>>>(
            W2, w2t_hi, w2t_lo, H_DIM, R_DIM);
    }
    // 1) h = relu(batch @ W1 + b1) -> half hi
    {
        dim3 grid(H_DIM / 128, M_TOT / 128);   // (8, 128)
        mma_gemm<0><<<grid, 256, MMA_SMEM>>>(
            a_hi, nullptr, w1t_hi, w1t_lo, b1, nullptr, h_hi, nullptr, D_DIM, H_DIM);
    }
    // 2) t = relu(h @ W2 + b2) -> half hi/lo + per-row squared norms
    {
        dim3 grid(R_DIM / 128, M_TOT / 128);   // (1, 128)
        mma_gemm<1><<<grid, 256, MMA_SMEM>>>(
            h_hi, nullptr, w2t_hi, w2t_lo, b2, sq_ptr, t_hi, t_lo, H_DIM, R_DIM);
    }
    // 3) pairwise distances: out[b,i,j] = max(sq_i + sq_j - 2 t_i.t_j, 0)
    {
        dim3 grid(L_DIM / 128, L_DIM / 128, B_DIM);   // (8, 8, 16)
        mma_gemm<2><<<grid, 256, MMA_SMEM>>>(
            t_hi, t_lo, t_hi, t_lo, sq_ptr, out, nullptr, nullptr, R_DIM, L_DIM);
    }
}